// round 15
// baseline (speedup 1.0000x reference)
#include <cuda_runtime.h>
#include <cstdint>

// KernelRepeatLinear: out[b,e,j] = bias[j] + sum_k weight[k,j] * P[b, e-7+k, j]
// P[b,e,j] = sum_{i<=j} x[b,e,i] * dv^(j-i)   (decayed inclusive prefix scan over dim)
#define Bv 8
#define Ev 2048
#define Sv 512
#define Kv 8
#define HALO (Kv - 1)
#define TE 16                 // output E-rows per FIR block
#define ROWS (TE + HALO)

typedef unsigned long long u64;

// 33.5 MB global scratch for scanned rows P
__device__ float g_P[(size_t)Bv * Ev * Sv];

#define FMA_F32X2(d, a, b, c) \
    asm("fma.rn.f32x2 %0, %1, %2, %3;" : "=l"(d) : "l"(a), "l"(b), "l"(c))

// ---------------- Kernel 1: decayed prefix scan of ONE batch (warp/row) -------
__global__ __launch_bounds__(256, 5)
void krl_scan15(const float* __restrict__ xB,     // x + b*Ev*Sv
                float* __restrict__ pB,           // g_P + b*Ev*Sv
                const float* __restrict__ decay)
{
    const int lane = threadIdx.x & 31;
    const int warp = threadIdx.x >> 5;
    const int row  = blockIdx.x * 8 + warp;       // e in [0, Ev)

    float dv = decay[1];
    dv = fminf(1.0f, fmaxf(0.9f, dv));
    const float dv2 = dv * dv;
    const float dv3 = dv2 * dv;
    const float dv4 = dv2 * dv2;
    const float dv8 = dv4 * dv4;
    const float dv16 = dv8 * dv8;

    const float4* src = (const float4*)(xB + (size_t)row * Sv);
    float4 a[4];
    #pragma unroll
    for (int q = 0; q < 4; ++q) a[q] = src[4 * lane + q];

    float p = 0.f;
    #pragma unroll
    for (int q = 0; q < 4; ++q) {
        p = fmaf(dv, p, a[q].x); a[q].x = p;
        p = fmaf(dv, p, a[q].y); a[q].y = p;
        p = fmaf(dv, p, a[q].z); a[q].z = p;
        p = fmaf(dv, p, a[q].w); a[q].w = p;
    }
    float s = p;
    float f = dv16;
    #pragma unroll
    for (int d = 1; d < 32; d <<= 1) {
        float o = __shfl_up_sync(0xffffffffu, s, d);
        if (lane >= d) s = fmaf(f, o, s);
        f = f * f;
    }
    float carry = __shfl_up_sync(0xffffffffu, s, 1);
    if (lane == 0) carry = 0.f;

    float4* dst = (float4*)(pB + (size_t)row * Sv);
    float cq = carry * dv;
    #pragma unroll
    for (int q = 0; q < 4; ++q) {
        a[q].x = a[q].x + cq;
        a[q].y = fmaf(cq, dv,  a[q].y);
        a[q].z = fmaf(cq, dv2, a[q].z);
        a[q].w = fmaf(cq, dv3, a[q].w);
        dst[4 * lane + q] = a[q];
        cq = cq * dv4;
    }
}

// ---------------- Kernel 2: rolling scatter FIR for ONE batch ------------------
__global__ __launch_bounds__(256, 4)
void krl_fir15(const float* __restrict__ pB,      // g_P + b*Ev*Sv
               const float* __restrict__ weight,
               const float* __restrict__ bias,
               float* __restrict__ outB)          // out + b*Ev*Sv
{
    const int jq = threadIdx.x;                    // float2 column
    const int e0 = blockIdx.x * TE;

    u64 wv[Kv];
    #pragma unroll
    for (int k = 0; k < Kv; ++k)
        wv[k] = ((const u64*)(weight + k * Sv))[jq];
    const u64 bv = ((const u64*)bias)[jq];

    const int gBase = e0 - HALO;
    const u64* Pb = (const u64*)(pB + (size_t)gBase * Sv);

    u64 v[4];
    #pragma unroll
    for (int j = 0; j < 4; ++j)
        v[j] = (gBase + j >= 0) ? Pb[(size_t)j * (Sv / 2) + jq] : 0ull;

    u64* outp = (u64*)(outB + (size_t)e0 * Sv);

    u64 acc[8];
    #pragma unroll
    for (int o = 0; o < 8; ++o) acc[o] = bv;

    #pragma unroll
    for (int i = 0; i < ROWS; ++i) {
        const u64 vcur = v[i & 3];
        if (i + 4 < ROWS)
            v[i & 3] = (gBase + i + 4 >= 0)
                         ? Pb[(size_t)(i + 4) * (Sv / 2) + jq] : 0ull;
        #pragma unroll
        for (int k = 0; k < 8; ++k) {
            const int o = i - k;
            if (o >= 0 && o < TE)
                FMA_F32X2(acc[o & 7], wv[k], vcur, acc[o & 7]);
        }
        if (i >= HALO) {
            const int o = i - HALO;
            outp[(size_t)o * (Sv / 2) + jq] = acc[o & 7];
            acc[o & 7] = bv;
        }
    }
}

// ---------------- host: two-stream pipelined launch (graph-capturable) --------
static cudaStream_t g_sS = nullptr, g_sF = nullptr;
static cudaEvent_t  g_evRoot = nullptr, g_evScan[Bv], g_evS = nullptr, g_evF = nullptr;

extern "C" void kernel_launch(void* const* d_in, const int* in_sizes, int n_in,
                              void* d_out, int out_size)
{
    const float* x      = (const float*)d_in[0];  // (B, E, S)
    const float* weight = (const float*)d_in[1];  // (K, S)
    const float* bias   = (const float*)d_in[2];  // (S,)
    const float* decay  = (const float*)d_in[3];  // (2, 1)
    float* out          = (float*)d_out;          // (B, E, S)

    if (!g_sS) {                                   // one-time infra (no device mem)
        cudaStreamCreateWithFlags(&g_sS, cudaStreamNonBlocking);
        cudaStreamCreateWithFlags(&g_sF, cudaStreamNonBlocking);
        cudaEventCreateWithFlags(&g_evRoot, cudaEventDisableTiming);
        cudaEventCreateWithFlags(&g_evS,    cudaEventDisableTiming);
        cudaEventCreateWithFlags(&g_evF,    cudaEventDisableTiming);
        for (int i = 0; i < Bv; ++i)
            cudaEventCreateWithFlags(&g_evScan[i], cudaEventDisableTiming);
    }

    float* P;
    cudaGetSymbolAddress((void**)&P, g_P);

    // fork both worker streams off the (capturing) default stream
    cudaEventRecord(g_evRoot, 0);
    cudaStreamWaitEvent(g_sS, g_evRoot, 0);
    cudaStreamWaitEvent(g_sF, g_evRoot, 0);

    for (int b = 0; b < Bv; ++b) {
        const size_t off = (size_t)b * Ev * Sv;
        krl_scan15<<<Ev / 8, 256, 0, g_sS>>>(x + off, P + off, decay);
        cudaEventRecord(g_evScan[b], g_sS);
        cudaStreamWaitEvent(g_sF, g_evScan[b], 0);
        krl_fir15<<<Ev / TE, 256, 0, g_sF>>>(P + off, weight, bias, out + off);
    }

    // join both streams back into the default stream
    cudaEventRecord(g_evS, g_sS);
    cudaEventRecord(g_evF, g_sF);
    cudaStreamWaitEvent(0, g_evS, 0);
    cudaStreamWaitEvent(0, g_evF, 0);
}

// round 16
// speedup vs baseline: 1.5582x; 1.5582x over previous
#include <cuda_runtime.h>
#include <cstdint>

// KernelRepeatLinear: out[b,e,j] = bias[j] + sum_k weight[k,j] * P[b, e-7+k, j]
// P[b,e,j] = sum_{i<=j} x[b,e,i] * dv^(j-i)   (decayed inclusive prefix scan over dim)
#define Bv 8
#define Ev 2048
#define Sv 512
#define Kv 8
#define HALO (Kv - 1)
#define TE 16
#define ROWS (TE + HALO)          // 23 rows per tile
#define THREADS 256
#define TPB 2                     // tiles per block (double buffer)
#define NTILES (Bv * (Ev / TE))   // 1024
#define GRID (NTILES / TPB)       // 512
#define BUF_FLOATS (ROWS * Sv)
#define SMEM_BYTES (2 * BUF_FLOATS * 4 + 16)

typedef unsigned long long u64;

// packed fp32x2 FMA (Blackwell)
#define FMA_F32X2(d, a, b, c) \
    asm("fma.rn.f32x2 %0, %1, %2, %3;" : "=l"(d) : "l"(a), "l"(b), "l"(c))

__device__ __forceinline__ void mbar_wait(uint32_t addr, int phase)
{
    uint32_t done;
    asm volatile(
        "{\n\t.reg .pred p;\n\t"
        "mbarrier.try_wait.parity.acquire.cta.shared::cta.b64 p, [%1], %2;\n\t"
        "selp.b32 %0, 1, 0, p;\n\t}"
        : "=r"(done) : "r"(addr), "r"(phase) : "memory");
    if (!done) {
        asm volatile(
            "{\n\t.reg .pred P1;\n\t"
            "WAIT_LOOP_%=:\n\t"
            "mbarrier.try_wait.parity.acquire.cta.shared::cta.b64 P1, [%0], %1, 0x989680;\n\t"
            "@P1 bra.uni WAIT_DONE_%=;\n\t"
            "bra.uni WAIT_LOOP_%=;\n\t"
            "WAIT_DONE_%=:\n\t}"
            :: "r"(addr), "r"(phase) : "memory");
    }
}

__global__ __launch_bounds__(THREADS, 2)
void krl_fused16(const float* __restrict__ x,
                 const float* __restrict__ weight,
                 const float* __restrict__ bias,
                 const float* __restrict__ decay,
                 float* __restrict__ out)
{
    extern __shared__ __align__(16) float smem[];
    float* const buf0 = smem;
    float* const buf1 = smem + BUF_FLOATS;

    const int tid  = threadIdx.x;
    const int lane = tid & 31;
    const int warp = tid >> 5;

    uint32_t smem_base, mbar_addr;
    {
        uint64_t tmp;
        asm("cvta.to.shared.u64 %0, %1;" : "=l"(tmp) : "l"(smem));
        smem_base = (uint32_t)tmp;
        mbar_addr = smem_base + 2u * BUF_FLOATS * 4u;
    }

    // init both buffer barriers
    if (tid < 2)
        asm volatile("mbarrier.init.shared.b64 [%0], %1;"
                     :: "r"(mbar_addr + 8u * tid), "r"(1) : "memory");
    __syncthreads();

    float dv = decay[1];
    dv = fminf(1.0f, fmaxf(0.9f, dv));
    const float dv2 = dv * dv;
    const float dv3 = dv2 * dv;
    const float dv4 = dv2 * dv2;
    const float dv8 = dv4 * dv4;
    const float dv16 = dv8 * dv8;

    // weights + bias in registers (loaded once, reused for both tiles)
    const int jq = tid;                            // float2 column, 0..255
    u64 wv[Kv];
    #pragma unroll
    for (int k = 0; k < Kv; ++k)
        wv[k] = ((const u64*)(weight + k * Sv))[jq];
    const u64 bv = ((const u64*)bias)[jq];

    // issue TMA for a tile into buffer bi; all threads zero halo rows if any
    auto issue_tile = [&](int tile, int bi) {
        const int b   = tile >> 7;                 // tile / 128
        const int e0  = (tile & 127) * TE;
        const int gfw = e0 - HALO;                 // first wanted global row
        const int dstRow = (gfw < 0) ? -gfw : 0;   // 7 on first tile of a batch
        const uint32_t bufOff = (uint32_t)bi * BUF_FLOATS * 4u;
        if (tid == 0) {
            const uint32_t bytes = (uint32_t)(ROWS - dstRow) * Sv * 4u;
            const uint32_t ba = mbar_addr + 8u * bi;
            asm volatile("mbarrier.arrive.expect_tx.shared.b64 _, [%0], %1;"
                         :: "r"(ba), "r"(bytes) : "memory");
            asm volatile("cp.async.bulk.shared::cta.global.mbarrier::complete_tx::bytes "
                         "[%0], [%1], %2, [%3];"
                         :: "r"(smem_base + bufOff + (uint32_t)dstRow * Sv * 4u),
                            "l"(x + ((size_t)b * Ev + gfw + dstRow) * Sv),
                            "r"(bytes), "r"(ba) : "memory");
        }
        if (dstRow != 0) {
            float4* z = (float4*)(smem + (size_t)bi * BUF_FLOATS);
            for (int i = tid; i < dstRow * (Sv / 4); i += THREADS)
                z[i] = make_float4(0.f, 0.f, 0.f, 0.f);
        }
    };

    // prologue: start tile 0's load
    issue_tile(blockIdx.x, 0);

    int ph0 = 0, ph1 = 0;

    #pragma unroll
    for (int it = 0; it < TPB; ++it) {
        const int cur  = it & 1;
        const int tile = blockIdx.x + GRID * it;
        const int b    = tile >> 7;
        const int e0   = (tile & 127) * TE;
        float* const shP = cur ? buf1 : buf0;

        // overlap: start next tile's load into the other buffer
        // (safe: that buffer's previous FIR finished before last __syncthreads)
        if (it + 1 < TPB)
            issue_tile(blockIdx.x + GRID * (it + 1), 1 - cur);

        // wait for this tile's data
        if (cur == 0) { mbar_wait(mbar_addr, ph0);      ph0 ^= 1; }
        else          { mbar_wait(mbar_addr + 8u, ph1); ph1 ^= 1; }
        __syncthreads();   // halo zeros visible; all warps past the wait

        // -------- Phase 1: in-place decayed prefix scan (warp per row) --------
        for (int r = warp; r < ROWS; r += 8) {
            float4* rowp = (float4*)(shP + r * Sv);
            float4 a[4];
            #pragma unroll
            for (int q = 0; q < 4; ++q) a[q] = rowp[4 * lane + q];

            float p = 0.f;
            #pragma unroll
            for (int q = 0; q < 4; ++q) {
                p = fmaf(dv, p, a[q].x); a[q].x = p;
                p = fmaf(dv, p, a[q].y); a[q].y = p;
                p = fmaf(dv, p, a[q].z); a[q].z = p;
                p = fmaf(dv, p, a[q].w); a[q].w = p;
            }
            float s = p;
            float f = dv16;
            #pragma unroll
            for (int d = 1; d < 32; d <<= 1) {
                float o = __shfl_up_sync(0xffffffffu, s, d);
                if (lane >= d) s = fmaf(f, o, s);
                f = f * f;
            }
            float carry = __shfl_up_sync(0xffffffffu, s, 1);
            if (lane == 0) carry = 0.f;

            float cq = carry * dv;                 // carry * dv^(4q+1)
            #pragma unroll
            for (int q = 0; q < 4; ++q) {
                a[q].x = a[q].x + cq;
                a[q].y = fmaf(cq, dv,  a[q].y);
                a[q].z = fmaf(cq, dv2, a[q].z);
                a[q].w = fmaf(cq, dv3, a[q].w);
                rowp[4 * lane + q] = a[q];
                cq = cq * dv4;
            }
        }
        __syncthreads();

        // -------- Phase 2: rolling scatter FIR, 8 rotating independent accs ---
        u64* outp = (u64*)(out + ((size_t)b * Ev + e0) * Sv);

        u64 acc[8];
        #pragma unroll
        for (int o = 0; o < 8; ++o) acc[o] = bv;

        u64 vcur = ((const u64*)shP)[jq];
        #pragma unroll
        for (int i = 0; i < ROWS; ++i) {
            u64 vnext = 0ull;
            if (i < ROWS - 1)
                vnext = ((const u64*)(shP + (i + 1) * Sv))[jq];
            #pragma unroll
            for (int k = 0; k < 8; ++k) {
                const int o = i - k;
                if (o >= 0 && o < TE)
                    FMA_F32X2(acc[o & 7], wv[k], vcur, acc[o & 7]);
            }
            if (i >= HALO) {                        // out row (i-7) complete
                const int o = i - HALO;
                outp[(size_t)o * (Sv / 2) + jq] = acc[o & 7];
                acc[o & 7] = bv;                    // recycle for out row o+8
            }
            vcur = vnext;
        }
        __syncthreads();   // buffer safe for reuse by the next TMA issue
    }
}

extern "C" void kernel_launch(void* const* d_in, const int* in_sizes, int n_in,
                              void* d_out, int out_size)
{
    const float* x      = (const float*)d_in[0];  // (B, E, S)
    const float* weight = (const float*)d_in[1];  // (K, S)
    const float* bias   = (const float*)d_in[2];  // (S,)
    const float* decay  = (const float*)d_in[3];  // (2, 1)
    float* out          = (float*)d_out;          // (B, E, S)

    cudaFuncSetAttribute(krl_fused16,
                         cudaFuncAttributeMaxDynamicSharedMemorySize, SMEM_BYTES);
    krl_fused16<<<GRID, THREADS, SMEM_BYTES>>>(x, weight, bias, decay, out);
}

// round 17
// speedup vs baseline: 1.8765x; 1.2043x over previous
#include <cuda_runtime.h>
#include <cstdint>

// KernelRepeatLinear: out[b,e,j] = bias[j] + sum_k weight[k,j] * P[b, e-7+k, j]
// P[b,e,j] = sum_{i<=j} x[b,e,i] * dv^(j-i)   (decayed inclusive prefix scan over dim)
#define Bv 8
#define Ev 2048
#define Sv 512
#define Kv 8
#define HALO (Kv - 1)
#define TE 16
#define ROWS (TE + HALO)          // 23 scan rows consumed per FIR tile
#define RING 24                   // smem ring slots (48 KB)
#define STRIP 32                  // output rows per block (2 chained tiles)
#define THREADS 256
#define GRID (Bv * (Ev / STRIP))  // 512
#define SMEM_BYTES (RING * Sv * 4 + 16)

typedef unsigned long long u64;

// packed fp32x2 FMA (Blackwell)
#define FMA_F32X2(d, a, b, c) \
    asm("fma.rn.f32x2 %0, %1, %2, %3;" : "=l"(d) : "l"(a), "l"(b), "l"(c))

__device__ __forceinline__ void mbar_wait_p0(uint32_t addr)
{
    uint32_t done;
    asm volatile(
        "{\n\t.reg .pred p;\n\t"
        "mbarrier.try_wait.parity.acquire.cta.shared::cta.b64 p, [%1], %2;\n\t"
        "selp.b32 %0, 1, 0, p;\n\t}"
        : "=r"(done) : "r"(addr), "r"(0) : "memory");
    if (!done) {
        asm volatile(
            "{\n\t.reg .pred P1;\n\t"
            "WAIT_LOOP_%=:\n\t"
            "mbarrier.try_wait.parity.acquire.cta.shared::cta.b64 P1, [%0], %1, 0x989680;\n\t"
            "@P1 bra.uni WAIT_DONE_%=;\n\t"
            "bra.uni WAIT_LOOP_%=;\n\t"
            "WAIT_DONE_%=:\n\t}"
            :: "r"(addr), "r"(0) : "memory");
    }
}

// decayed prefix scan of one 512-float row in smem, in place (warp-collective)
__device__ __forceinline__ void scan_row(float* rowp, int lane,
                                         float dv, float dv2, float dv3,
                                         float dv4, float dv16)
{
    float4* rp = (float4*)rowp;
    float4 a[4];
    #pragma unroll
    for (int q = 0; q < 4; ++q) a[q] = rp[4 * lane + q];

    float p = 0.f;
    #pragma unroll
    for (int q = 0; q < 4; ++q) {
        p = fmaf(dv, p, a[q].x); a[q].x = p;
        p = fmaf(dv, p, a[q].y); a[q].y = p;
        p = fmaf(dv, p, a[q].z); a[q].z = p;
        p = fmaf(dv, p, a[q].w); a[q].w = p;
    }
    float s = p;
    float f = dv16;
    #pragma unroll
    for (int d = 1; d < 32; d <<= 1) {
        float o = __shfl_up_sync(0xffffffffu, s, d);
        if (lane >= d) s = fmaf(f, o, s);
        f = f * f;
    }
    float carry = __shfl_up_sync(0xffffffffu, s, 1);
    if (lane == 0) carry = 0.f;

    float cq = carry * dv;                         // carry * dv^(4q+1)
    #pragma unroll
    for (int q = 0; q < 4; ++q) {
        a[q].x = a[q].x + cq;
        a[q].y = fmaf(cq, dv,  a[q].y);
        a[q].z = fmaf(cq, dv2, a[q].z);
        a[q].w = fmaf(cq, dv3, a[q].w);
        rp[4 * lane + q] = a[q];
        cq = cq * dv4;
    }
}

// rolling scatter FIR over ring slots (BASE+i)%RING, i=0..22 (compile-time slots)
template <int BASE>
__device__ __forceinline__ void fir_tile(const float* ringf, int jq,
                                         const u64* wv, u64 bv, u64* outp)
{
    u64 acc[8];
    #pragma unroll
    for (int o = 0; o < 8; ++o) acc[o] = bv;

    u64 vcur = ((const u64*)(ringf + (BASE % RING) * Sv))[jq];
    #pragma unroll
    for (int i = 0; i < ROWS; ++i) {
        u64 vnext = 0ull;
        if (i < ROWS - 1)
            vnext = ((const u64*)(ringf + ((BASE + i + 1) % RING) * Sv))[jq];
        #pragma unroll
        for (int k = 0; k < 8; ++k) {
            const int o = i - k;
            if (o >= 0 && o < TE)
                FMA_F32X2(acc[o & 7], wv[k], vcur, acc[o & 7]);
        }
        if (i >= HALO) {                           // out row (i-7) complete
            const int o = i - HALO;
            outp[(size_t)o * (Sv / 2) + jq] = acc[o & 7];
            acc[o & 7] = bv;                       // recycle for out row o+8
        }
        vcur = vnext;
    }
}

__global__ __launch_bounds__(THREADS, 4)
void krl_fused17(const float* __restrict__ x,
                 const float* __restrict__ weight,
                 const float* __restrict__ bias,
                 const float* __restrict__ decay,
                 float* __restrict__ out)
{
    extern __shared__ __align__(16) float ringf[];   // RING*Sv floats + 2 mbars

    const int tid  = threadIdx.x;
    const int lane = tid & 31;
    const int warp = tid >> 5;

    const int b  = blockIdx.x >> 6;                  // / 64 strips per batch
    const int s  = blockIdx.x & 63;
    const int e0 = s * STRIP;

    const float* xb = x + (size_t)b * Ev * Sv;

    uint32_t ring_addr, mbar_addr;
    {
        uint64_t tmp;
        asm("cvta.to.shared.u64 %0, %1;" : "=l"(tmp) : "l"(ringf));
        ring_addr = (uint32_t)tmp;
        mbar_addr = ring_addr + (uint32_t)RING * Sv * 4u;
    }

    if (tid < 2)
        asm volatile("mbarrier.init.shared.b64 [%0], %1;"
                     :: "r"(mbar_addr + 8u * tid), "r"(1) : "memory");
    const int dstRow = (s == 0) ? HALO : 0;          // halo slots to zero
    if (dstRow != 0) {
        float4* z = (float4*)ringf;
        for (int i = tid; i < dstRow * (Sv / 4); i += THREADS)
            z[i] = make_float4(0.f, 0.f, 0.f, 0.f);
    }
    __syncthreads();                                 // mbars + zeros visible

    // ---- tile 0 TMA: rows e0-7+dstRow .. e0+15 -> slots dstRow..22 ----
    if (tid == 0) {
        const uint32_t bytes = (uint32_t)(ROWS - dstRow) * Sv * 4u;
        asm volatile("mbarrier.arrive.expect_tx.shared.b64 _, [%0], %1;"
                     :: "r"(mbar_addr), "r"(bytes) : "memory");
        asm volatile("cp.async.bulk.shared::cta.global.mbarrier::complete_tx::bytes "
                     "[%0], [%1], %2, [%3];"
                     :: "r"(ring_addr + (uint32_t)dstRow * Sv * 4u),
                        "l"(xb + (size_t)(e0 - HALO + dstRow) * Sv),
                        "r"(bytes), "r"(mbar_addr) : "memory");
    }

    float dv = decay[1];
    dv = fminf(1.0f, fmaxf(0.9f, dv));
    const float dv2 = dv * dv;
    const float dv3 = dv2 * dv;
    const float dv4 = dv2 * dv2;
    const float dv8 = dv4 * dv4;
    const float dv16 = dv8 * dv8;

    // weights + bias hoisted (latency hides behind the TMA wait)
    const int jq = tid;                              // float2 column 0..255
    u64 wv[Kv];
    #pragma unroll
    for (int k = 0; k < Kv; ++k)
        wv[k] = ((const u64*)(weight + k * Sv))[jq];
    const u64 bv = ((const u64*)bias)[jq];

    if (warp == 0) mbar_wait_p0(mbar_addr);
    __syncthreads();

    // ---- phase 1, tile 0: scan slots 0..22 ----
    for (int r = warp; r < ROWS; r += 8)
        scan_row(ringf + r * Sv, lane, dv, dv2, dv3, dv4, dv16);
    __syncthreads();

    // ---- phase 2, tile 0: outputs e0 .. e0+15 ----
    fir_tile<0>(ringf, jq, wv, bv, (u64*)(out + ((size_t)b * Ev + e0) * Sv));
    __syncthreads();                                 // slots 0..14, 23 now free

    // ---- tile 1 TMA: rows e0+16..e0+31 -> slots 23, 0..14 (ring wrap) ----
    if (tid == 0) {
        asm volatile("mbarrier.arrive.expect_tx.shared.b64 _, [%0], %1;"
                     :: "r"(mbar_addr + 8u), "r"((uint32_t)(TE * Sv * 4u)) : "memory");
        asm volatile("cp.async.bulk.shared::cta.global.mbarrier::complete_tx::bytes "
                     "[%0], [%1], %2, [%3];"
                     :: "r"(ring_addr + 23u * Sv * 4u),
                        "l"(xb + (size_t)(e0 + 16) * Sv),
                        "r"((uint32_t)(Sv * 4u)), "r"(mbar_addr + 8u) : "memory");
        asm volatile("cp.async.bulk.shared::cta.global.mbarrier::complete_tx::bytes "
                     "[%0], [%1], %2, [%3];"
                     :: "r"(ring_addr),
                        "l"(xb + (size_t)(e0 + 17) * Sv),
                        "r"((uint32_t)(15 * Sv * 4u)), "r"(mbar_addr + 8u) : "memory");
    }
    if (warp == 0) mbar_wait_p0(mbar_addr + 8u);
    __syncthreads();

    // ---- phase 1, tile 1: scan 16 new rows (l = 23..38 -> slots 23, 0..14) ----
    #pragma unroll
    for (int it = 0; it < 2; ++it) {
        const int l = 23 + warp + 8 * it;            // 23..38
        const int slot = (l < RING) ? l : l - RING;
        scan_row(ringf + slot * Sv, lane, dv, dv2, dv3, dv4, dv16);
    }
    __syncthreads();

    // ---- phase 2, tile 1: scan window l=16..38 -> slots (16+i)%24 ----
    fir_tile<16>(ringf, jq, wv, bv, (u64*)(out + ((size_t)b * Ev + e0 + 16) * Sv));
}

extern "C" void kernel_launch(void* const* d_in, const int* in_sizes, int n_in,
                              void* d_out, int out_size)
{
    const float* x      = (const float*)d_in[0];  // (B, E, S)
    const float* weight = (const float*)d_in[1];  // (K, S)
    const float* bias   = (const float*)d_in[2];  // (S,)
    const float* decay  = (const float*)d_in[3];  // (2, 1)
    float* out          = (float*)d_out;          // (B, E, S)

    cudaFuncSetAttribute(krl_fused17,
                         cudaFuncAttributeMaxDynamicSharedMemorySize, SMEM_BYTES);
    krl_fused17<<<GRID, THREADS, SMEM_BYTES>>>(x, weight, bias, decay, out);
}